// round 15
// baseline (speedup 1.0000x reference)
#include <cuda_runtime.h>
#include <cstdint>

#define B_ 256
#define T_ 2048
#define I_ 50
#define H_ 116
#define O_ 50
#define N_TOT (B_ * T_)

typedef unsigned long long u64;

// Device scratch (static allocation = allowed)
__device__ float g_hs[(size_t)N_TOT * H_];   // hidden states [N, H]
__device__ float g_dummy;

// ---------------- packed f32x2 helpers (Blackwell) ----------------
__device__ __forceinline__ u64 fma2(u64 a, u64 b, u64 c) {
    u64 d;
    asm("fma.rn.f32x2 %0, %1, %2, %3;" : "=l"(d) : "l"(a), "l"(b), "l"(c));
    return d;
}
__device__ __forceinline__ u64 add2(u64 a, u64 b) {
    u64 d;
    asm("add.rn.f32x2 %0, %1, %2;" : "=l"(d) : "l"(a), "l"(b));
    return d;
}
__device__ __forceinline__ float pair_sum(u64 a) {
    float lo = __uint_as_float((unsigned)(a & 0xFFFFFFFFull));
    float hi = __uint_as_float((unsigned)(a >> 32));
    return lo + hi;
}
__device__ __forceinline__ void cp16(void* smem, const void* gmem) {
    unsigned s = (unsigned)__cvta_generic_to_shared(smem);
    asm volatile("cp.async.ca.shared.global [%0], [%1], 16;" :: "r"(s), "l"(gmem));
}
#define CP_COMMIT() asm volatile("cp.async.commit_group;")
#define CP_WAIT(n)  asm volatile("cp.async.wait_group %0;" :: "n"(n))

// ============ fused kernel: h(t+1) = relu(W_ih x(t) + b + W_hh h(t)) =======
// 256 CTAs x 256 threads; one batch row per CTA, 2 CTAs/SM.
// Lane pair (2j,2j+1) computes h[j]: half0 owns W_hh[j][0:60) + W_ih[j][0:26)
// (+bias); half1 owns W_hh[j][60:116) + W_ih[j][26:50). xp(t+1) is computed
// packed each step (off the h critical chain, fills issue bubbles) and folds
// into the next step's a0; one pair_sum+shfl reduces h-dot AND xp together.
// Lanes [232,256) additionally stage x: __ldg x(t+6) into a 4-deep register
// ring, STS x(t+2) into a 4-slot smem ring (plain loads/stores, no waits).
// CONVERGENCE: the step body (dot, pair_sum, shfl, xp partial) is executed by
// ALL 256 threads — stager lanes carry zero weights; results unused.
// NOTE: macro-local time index is t_ (NOT t) — avoids the shadowing self-init
// bug (`const int t = (t+1);`) that broke R12/R13.
__global__ void __launch_bounds__(256, 2) xr_kernel(
    const float* __restrict__ x,
    const float* __restrict__ W_ih,
    const float* __restrict__ b_ih,
    const float* __restrict__ W_hh,
    const float* __restrict__ b_hh)
{
    __shared__ __align__(16) float h_s[2][128];   // ping-pong, 116 used
    __shared__ __align__(16) float x_s[4][52];    // ring; [50,52) stays zero

    const int s    = threadIdx.x;
    const int j    = s >> 1;
    const int half = s & 1;
    const int b    = blockIdx.x;
    const bool comp = (s < 232);                  // j < 116
    const bool even = comp && (half == 0);
    const bool stg  = (s >= 232);
    const int u = s - 232;                        // stager lane 0..23

    h_s[0][s & 127] = 0.f;
    h_s[1][s & 127] = 0.f;
    if (s < 8) x_s[s >> 1][50 + (s & 1)] = 0.f;   // zero pads (never rewritten)

    // ---- weights (registers); zero for inactive/stager lanes ----
    u64 w[30];
    u64 wi[13];
    float bias = 0.f;
    #pragma unroll
    for (int q = 0; q < 30; q++) w[q] = 0ull;
    #pragma unroll
    for (int q = 0; q < 13; q++) wi[q] = 0ull;
    if (comp) {
        const u64* ws = reinterpret_cast<const u64*>(W_hh + j * H_ + 60 * half);
        const int nw = 30 - 2 * half;
        #pragma unroll
        for (int q = 0; q < 30; q++) if (q < nw) w[q] = ws[q];
        const u64* wis = reinterpret_cast<const u64*>(W_ih + j * I_ + 26 * half);
        const int ni = 13 - half;
        #pragma unroll
        for (int q = 0; q < 13; q++) if (q < ni) wi[q] = wis[q];
        if (half == 0) bias = b_ih[j] + b_hh[j];
    }

    // ---- stager prologue: x(0),x(1) -> smem; ring = x(2..5) ----
    const float* xb = x + (size_t)b * T_ * I_;    // rows 200B, 8B-aligned
    u64 r0 = 0, r1 = 0, r2 = 0, r3 = 0;
    u64 q0 = 0, q1 = 0, q2 = 0, q3 = 0;           // lane u==0 extra (idx 24)
    if (stg) {
        #pragma unroll
        for (int t0 = 0; t0 < 2; t0++) {
            const u64* src = reinterpret_cast<const u64*>(xb + t0 * I_);
            reinterpret_cast<u64*>(x_s[t0])[u] = src[u];
            if (u == 0) reinterpret_cast<u64*>(x_s[t0])[24] = src[24];
        }
        const u64* s2 = reinterpret_cast<const u64*>(xb + 2 * I_);
        const u64* s3 = reinterpret_cast<const u64*>(xb + 3 * I_);
        const u64* s4 = reinterpret_cast<const u64*>(xb + 4 * I_);
        const u64* s5 = reinterpret_cast<const u64*>(xb + 5 * I_);
        r0 = __ldg(s2 + u); r1 = __ldg(s3 + u);
        r2 = __ldg(s4 + u); r3 = __ldg(s5 + u);
        if (u == 0) { q0 = __ldg(s2 + 24); q1 = __ldg(s3 + 24);
                      q2 = __ldg(s4 + 24); q3 = __ldg(s5 + 24); }
    }
    __syncthreads();

    // ---- xp(0) partial (packed), seeded with bias on half0 ----
    u64 xpacc = (u64)__float_as_uint(bias);       // bias==0 except comp-half0
    {
        const u64* xv = reinterpret_cast<const u64*>(x_s[0]) + 13 * half;
        #pragma unroll
        for (int q = 0; q < 13; q++) xpacc = fma2(wi[q], xv[q], xpacc);
    }

    float* hsp = g_hs + (size_t)b * T_ * H_ + j;
    int p = 0;

#define XR_STEP(RR, QQ, T0)                                                  \
    {                                                                        \
        const int t_ = (T0);                                                 \
        if (stg) {                                                           \
            /* STS x(t_+2) from ring; LDG x(t_+6) into ring */               \
            u64* dst = reinterpret_cast<u64*>(x_s[(t_ + 2) & 3]);            \
            dst[u] = RR;                                                     \
            if (u == 0) dst[24] = QQ;                                        \
            if (t_ + 6 < T_) {                                               \
                const u64* src =                                             \
                    reinterpret_cast<const u64*>(xb + (t_ + 6) * I_);        \
                RR = __ldg(src + u);                                         \
                if (u == 0) QQ = __ldg(src + 24);                            \
            }                                                                \
        }                                                                    \
        /* ALL threads: h(t_+1) = relu(xp(t_) + W_hh h(t_)) */               \
        u64 a0 = xpacc, a1 = 0, a2 = 0, a3 = 0;                              \
        const ulonglong2* hv =                                               \
            reinterpret_cast<const ulonglong2*>(h_s[p]) + 15 * half;         \
        _Pragma("unroll")                                                    \
        for (int q = 0; q < 15; q++) {                                       \
            ulonglong2 v = hv[q];                                            \
            if (q & 1) { a2 = fma2(w[2 * q],     v.x, a2);                   \
                         a3 = fma2(w[2 * q + 1], v.y, a3); }                 \
            else       { a0 = fma2(w[2 * q],     v.x, a0);                   \
                         a1 = fma2(w[2 * q + 1], v.y, a1); }                 \
        }                                                                    \
        float part = pair_sum(add2(add2(a0, a1), add2(a2, a3)));             \
        float oth  = __shfl_xor_sync(0xFFFFFFFFu, part, 1);                  \
        if (even) {                                                          \
            float h = fmaxf(part + oth, 0.f);                                \
            h_s[p ^ 1][j] = h;                                               \
            hsp[0] = h; hsp += H_;                                           \
        }                                                                    \
        /* ALL threads: xp(t_+1) partial for next step */                    \
        xpacc = (u64)__float_as_uint(bias);                                  \
        {                                                                    \
            const u64* xv = reinterpret_cast<const u64*>(                    \
                                x_s[(t_ + 1) & 3]) + 13 * half;              \
            _Pragma("unroll")                                                \
            for (int q = 0; q < 13; q++)                                     \
                xpacc = fma2(wi[q], xv[q], xpacc);                           \
        }                                                                    \
        __syncthreads();                                                     \
        p ^= 1;                                                              \
    }

    for (int t = 0; t < T_; t += 4) {
        XR_STEP(r0, q0, t)
        XR_STEP(r1, q1, t + 1)
        XR_STEP(r2, q2, t + 2)
        XR_STEP(r3, q3, t + 3)
    }
#undef XR_STEP
}

// ================= FC GEMM: out[n,o] = hs[n,:]·W_fc[o,:] + b_fc[o] =========
// k-split lane pairs: lanes (2o, 2o+1) hold half of W_fc row o in regs,
// partials merged via shfl.bfly(1). 2 CTAs/SM.
#define FC_ROWS 16
#define FC_NT   (N_TOT / FC_ROWS)
__global__ void __launch_bounds__(256, 2) fc_kernel(
    const float* __restrict__ W_fc,
    const float* __restrict__ b_fc,
    float* __restrict__ out)
{
    __shared__ __align__(16) float hs_s[2][FC_ROWS * H_ + 4];

    const int tid  = threadIdx.x;
    const int o2   = tid & 127;
    const int o    = o2 >> 1;
    const int half = o2 & 1;
    const int g    = tid >> 7;
    const bool is_o = (o < O_);

    u64 w[30];
    #pragma unroll
    for (int q = 0; q < 30; q++) w[q] = 0ull;
    float bias = 0.f;
    if (is_o) {
        const u64* ws =
            reinterpret_cast<const u64*>(W_fc + o * H_ + 60 * half);
        const int nw = 30 - 2 * half;
        #pragma unroll
        for (int q = 0; q < 30; q++) if (q < nw) w[q] = ws[q];
        bias = b_fc[o];
    }

    const float* hs = g_hs;
    int tile = blockIdx.x;
    if (tile < FC_NT) {
        const float* src = hs + (size_t)tile * (FC_ROWS * H_);
        for (int i = tid; i < (FC_ROWS * H_) / 4; i += 256)
            cp16(&hs_s[0][4 * i], src + 4 * i);
    }
    CP_COMMIT();

    int pb = 0;
    for (; tile < FC_NT; tile += gridDim.x) {
        const int nxt = tile + gridDim.x;
        if (nxt < FC_NT) {
            const float* src = hs + (size_t)nxt * (FC_ROWS * H_);
            for (int i = tid; i < (FC_ROWS * H_) / 4; i += 256)
                cp16(&hs_s[pb ^ 1][4 * i], src + 4 * i);
        }
        CP_COMMIT();
        CP_WAIT(1);
        __syncthreads();

        #pragma unroll
        for (int i = 0; i < FC_ROWS / 2; i++) {
            const int row = 2 * i + g;
            const ulonglong2* hv = reinterpret_cast<const ulonglong2*>(
                hs_s[pb] + row * H_ + 60 * half);
            u64 a0 = 0, a1 = 0, a2 = 0, a3 = 0;
            #pragma unroll
            for (int q = 0; q < 15; q++) {
                ulonglong2 v = hv[q];
                if (q & 1) {
                    a2 = fma2(w[2 * q],     v.x, a2);
                    a3 = fma2(w[2 * q + 1], v.y, a3);
                } else {
                    a0 = fma2(w[2 * q],     v.x, a0);
                    a1 = fma2(w[2 * q + 1], v.y, a1);
                }
            }
            float part = pair_sum(add2(add2(a0, a1), add2(a2, a3)));
            float oth  = __shfl_xor_sync(0xFFFFFFFFu, part, 1);
            if (is_o && half == 0)
                out[(size_t)(tile * FC_ROWS + row) * O_ + o] =
                    part + oth + bias;
        }
        __syncthreads();
        pb ^= 1;
    }
}

// Probe kernels: occupy ncu capture slots so slot 4 = xr_kernel.
__global__ void probe_kernel() {
    if (threadIdx.x == 0 && blockIdx.x == 0) g_dummy = g_dummy;
}

// ---------------- launch ----------------
extern "C" void kernel_launch(void* const* d_in, const int* in_sizes, int n_in,
                              void* d_out, int out_size)
{
    const float* x    = (const float*)d_in[0];
    const float* W_ih = (const float*)d_in[1];
    const float* b_ih = (const float*)d_in[2];
    const float* W_hh = (const float*)d_in[3];
    const float* b_hh = (const float*)d_in[4];
    const float* W_fc = (const float*)d_in[5];
    const float* b_fc = (const float*)d_in[6];
    float* out = (float*)d_out;

    probe_kernel<<<1, 32>>>();
    probe_kernel<<<1, 32>>>();
    probe_kernel<<<1, 32>>>();
    xr_kernel<<<B_, 256>>>(x, W_ih, b_ih, W_hh, b_hh);
    fc_kernel<<<2048, 256>>>(W_fc, b_fc, out);
}

// round 16
// speedup vs baseline: 1.1210x; 1.1210x over previous
#include <cuda_runtime.h>
#include <cstdint>

#define B_ 256
#define T_ 2048
#define I_ 50
#define H_ 116
#define O_ 50
#define N_TOT (B_ * T_)

typedef unsigned long long u64;

// Device scratch (static allocation = allowed)
__device__ float g_xp[(size_t)N_TOT * H_];   // input projection [N, H]
__device__ float g_hs[(size_t)N_TOT * H_];   // hidden states    [N, H]
__device__ float g_dummy;

// ---------------- packed f32x2 helpers (Blackwell) ----------------
__device__ __forceinline__ u64 fma2(u64 a, u64 b, u64 c) {
    u64 d;
    asm("fma.rn.f32x2 %0, %1, %2, %3;" : "=l"(d) : "l"(a), "l"(b), "l"(c));
    return d;
}
__device__ __forceinline__ u64 add2(u64 a, u64 b) {
    u64 d;
    asm("add.rn.f32x2 %0, %1, %2;" : "=l"(d) : "l"(a), "l"(b));
    return d;
}
__device__ __forceinline__ float pair_sum(u64 a) {
    float lo = __uint_as_float((unsigned)(a & 0xFFFFFFFFull));
    float hi = __uint_as_float((unsigned)(a >> 32));
    return lo + hi;
}
__device__ __forceinline__ void cp16(void* smem, const void* gmem) {
    unsigned s = (unsigned)__cvta_generic_to_shared(smem);
    asm volatile("cp.async.ca.shared.global [%0], [%1], 16;" :: "r"(s), "l"(gmem));
}
__device__ __forceinline__ void cp8(void* smem, const void* gmem) {
    unsigned s = (unsigned)__cvta_generic_to_shared(smem);
    asm volatile("cp.async.ca.shared.global [%0], [%1], 8;" :: "r"(s), "l"(gmem));
}
#define CP_COMMIT() asm volatile("cp.async.commit_group;")
#define CP_WAIT(n)  asm volatile("cp.async.wait_group %0;" :: "n"(n))

// ================= xp GEMM: g_xp[n,j] = x[n,:]·W_ih[j,:] + b_ih[j]+b_hh[j] ==
#define XP_ROWS 32
#define XP_RPAD 52
#define XP_NT   (N_TOT / XP_ROWS)
__global__ void __launch_bounds__(256) xp_kernel(
    const float* __restrict__ x,
    const float* __restrict__ W_ih,
    const float* __restrict__ b_ih,
    const float* __restrict__ b_hh)
{
    __shared__ __align__(16) float xs[2][XP_ROWS * XP_RPAD];

    const int tid = threadIdx.x;
    const int j   = tid & 127;
    const int r2  = tid >> 7;
    const bool is_j = (j < H_);

    u64 wih[25];
    float bias = 0.f;
    if (is_j) {
        const u64* p = reinterpret_cast<const u64*>(W_ih + j * I_);
        #pragma unroll
        for (int q = 0; q < 25; q++) wih[q] = p[q];
        bias = b_ih[j] + b_hh[j];
    }

    auto stage = [&](int tile, int buf) {
        const float* src = x + (size_t)tile * (XP_ROWS * I_);
        for (int i = tid; i < XP_ROWS * 25; i += 256) {
            int row = i / 25, c = i - 25 * row;
            cp8(&xs[buf][row * XP_RPAD + 2 * c], src + row * I_ + 2 * c);
        }
    };

    int tile = blockIdx.x;
    if (tile < XP_NT) stage(tile, 0);
    CP_COMMIT();

    int pb = 0;
    for (; tile < XP_NT; tile += gridDim.x) {
        const int nxt = tile + gridDim.x;
        if (nxt < XP_NT) stage(nxt, pb ^ 1);
        CP_COMMIT();
        CP_WAIT(1);
        __syncthreads();

        if (is_j) {
            float* orow = g_xp + (size_t)tile * XP_ROWS * H_ + j;
            #pragma unroll 2
            for (int i = 0; i < XP_ROWS / 2; i++) {
                const int row = 2 * i + r2;
                const float* rbase = xs[pb] + row * XP_RPAD;
                const ulonglong2* av =
                    reinterpret_cast<const ulonglong2*>(rbase);
                u64 a0 = 0, a1 = 0, a2 = 0, a3 = 0;
                #pragma unroll
                for (int q = 0; q < 12; q++) {
                    ulonglong2 v = av[q];
                    if (q & 1) {
                        a2 = fma2(wih[2 * q],     v.x, a2);
                        a3 = fma2(wih[2 * q + 1], v.y, a3);
                    } else {
                        a0 = fma2(wih[2 * q],     v.x, a0);
                        a1 = fma2(wih[2 * q + 1], v.y, a1);
                    }
                }
                a0 = fma2(wih[24],
                          reinterpret_cast<const u64*>(rbase)[24], a0);
                orow[(size_t)row * H_] =
                    pair_sum(add2(add2(a0, a1), add2(a2, a3))) + bias;
            }
        }
        __syncthreads();
        pb ^= 1;
    }
}

// ================= recurrence (R8, measured 612us): ========================
// h(t+1) = relu(xp(t) + W_hh·h(t)). 256 CTAs x 128 threads, 1 row/CTA,
// 2 CTAs/SM. Thread j holds the FULL W_hh row j in registers; h(t) read via
// perfect-broadcast LDS.128; xp prefetched 2 steps ahead via __ldg.
__global__ void __launch_bounds__(128, 2) rnn_kernel(
    const float* __restrict__ W_hh)
{
    __shared__ __align__(16) float h_s[2][120];   // ping-pong, 116 used

    const int j = threadIdx.x;
    const int b = blockIdx.x;
    const bool comp = (j < H_);

    if (j < 120) { h_s[0][j] = 0.f; h_s[1][j] = 0.f; }

    u64 w[58];
    if (comp) {
        const u64* ws = reinterpret_cast<const u64*>(W_hh + j * H_);
        #pragma unroll
        for (int q = 0; q < 58; q++) w[q] = ws[q];
    }

    const float* xpb = g_xp + (size_t)b * T_ * H_ + j;
    float xpr0 = 0.f, xpr1 = 0.f;
    if (comp) { xpr0 = __ldg(xpb); xpr1 = __ldg(xpb + H_); }
    __syncthreads();

    float* hs_ptr = g_hs + (size_t)b * T_ * H_ + j;
    int p = 0;

#define RNN_STEP(XPR, TNEXT)                                                 \
    {                                                                        \
        u64 a0 = (u64)__float_as_uint(XPR);        /* consume xp(t) */       \
        if (comp && (TNEXT) < T_)                  /* refill, 2-step slack */\
            XPR = __ldg(xpb + (size_t)(TNEXT) * H_);                         \
        u64 a1 = 0, a2 = 0, a3 = 0;                                          \
        const ulonglong2* hv =                                               \
            reinterpret_cast<const ulonglong2*>(h_s[p]);                     \
        _Pragma("unroll")                                                    \
        for (int q = 0; q < 29; q++) {                                       \
            ulonglong2 v = hv[q];                                            \
            if (q & 1) { a2 = fma2(w[2 * q],     v.x, a2);                   \
                         a3 = fma2(w[2 * q + 1], v.y, a3); }                 \
            else       { a0 = fma2(w[2 * q],     v.x, a0);                   \
                         a1 = fma2(w[2 * q + 1], v.y, a1); }                 \
        }                                                                    \
        if (comp) {                                                          \
            float h = fmaxf(                                                 \
                pair_sum(add2(add2(a0, a1), add2(a2, a3))), 0.f);            \
            h_s[p ^ 1][j] = h;                                               \
            hs_ptr[0] = h; hs_ptr += H_;                                     \
        }                                                                    \
        __syncthreads();                                                     \
        p ^= 1;                                                              \
    }

    for (int t = 0; t < T_; t += 2) {
        RNN_STEP(xpr0, t + 2)
        RNN_STEP(xpr1, t + 3)
    }
#undef RNN_STEP
}

// ================= FC GEMM: out[n,o] = hs[n,:]·W_fc[o,:] + b_fc[o] =========
// k-split lane pairs: lanes (2o, 2o+1) hold half of W_fc row o in regs,
// partials merged via shfl.bfly(1). 2 CTAs/SM. FC_ROWS=32: barrier/staging
// amortized over 2x rows, 16 independent row-dots per thread per tile.
#define FC_ROWS 32
#define FC_NT   (N_TOT / FC_ROWS)
__global__ void __launch_bounds__(256, 2) fc_kernel(
    const float* __restrict__ W_fc,
    const float* __restrict__ b_fc,
    float* __restrict__ out)
{
    __shared__ __align__(16) float hs_s[2][FC_ROWS * H_ + 4];

    const int tid  = threadIdx.x;
    const int o2   = tid & 127;
    const int o    = o2 >> 1;
    const int half = o2 & 1;
    const int g    = tid >> 7;
    const bool is_o = (o < O_);

    u64 w[30];
    #pragma unroll
    for (int q = 0; q < 30; q++) w[q] = 0ull;
    float bias = 0.f;
    if (is_o) {
        const u64* ws =
            reinterpret_cast<const u64*>(W_fc + o * H_ + 60 * half);
        const int nw = 30 - 2 * half;
        #pragma unroll
        for (int q = 0; q < 30; q++) if (q < nw) w[q] = ws[q];
        bias = b_fc[o];
    }

    const float* hs = g_hs;
    int tile = blockIdx.x;
    if (tile < FC_NT) {
        const float* src = hs + (size_t)tile * (FC_ROWS * H_);
        for (int i = tid; i < (FC_ROWS * H_) / 4; i += 256)
            cp16(&hs_s[0][4 * i], src + 4 * i);
    }
    CP_COMMIT();

    int pb = 0;
    for (; tile < FC_NT; tile += gridDim.x) {
        const int nxt = tile + gridDim.x;
        if (nxt < FC_NT) {
            const float* src = hs + (size_t)nxt * (FC_ROWS * H_);
            for (int i = tid; i < (FC_ROWS * H_) / 4; i += 256)
                cp16(&hs_s[pb ^ 1][4 * i], src + 4 * i);
        }
        CP_COMMIT();
        CP_WAIT(1);
        __syncthreads();

        #pragma unroll
        for (int i = 0; i < FC_ROWS / 2; i++) {
            const int row = 2 * i + g;
            const ulonglong2* hv = reinterpret_cast<const ulonglong2*>(
                hs_s[pb] + row * H_ + 60 * half);
            u64 a0 = 0, a1 = 0, a2 = 0, a3 = 0;
            #pragma unroll
            for (int q = 0; q < 15; q++) {
                ulonglong2 v = hv[q];
                if (q & 1) {
                    a2 = fma2(w[2 * q],     v.x, a2);
                    a3 = fma2(w[2 * q + 1], v.y, a3);
                } else {
                    a0 = fma2(w[2 * q],     v.x, a0);
                    a1 = fma2(w[2 * q + 1], v.y, a1);
                }
            }
            float part = pair_sum(add2(add2(a0, a1), add2(a2, a3)));
            float oth  = __shfl_xor_sync(0xFFFFFFFFu, part, 1);
            if (is_o && half == 0)
                out[(size_t)(tile * FC_ROWS + row) * O_ + o] =
                    part + oth + bias;
        }
        __syncthreads();
        pb ^= 1;
    }
}

// Probe kernel: occupies the 3rd launch slot so the ncu capture (4th launch)
// lands on fc_kernel.
__global__ void probe_kernel() {
    if (threadIdx.x == 0 && blockIdx.x == 0) g_dummy = g_dummy;
}

// ---------------- launch ----------------
extern "C" void kernel_launch(void* const* d_in, const int* in_sizes, int n_in,
                              void* d_out, int out_size)
{
    const float* x    = (const float*)d_in[0];
    const float* W_ih = (const float*)d_in[1];
    const float* b_ih = (const float*)d_in[2];
    const float* W_hh = (const float*)d_in[3];
    const float* b_hh = (const float*)d_in[4];
    const float* W_fc = (const float*)d_in[5];
    const float* b_fc = (const float*)d_in[6];
    float* out = (float*)d_out;

    xp_kernel<<<4096, 256>>>(x, W_ih, b_ih, b_hh);
    rnn_kernel<<<B_, 128>>>(W_hh);
    probe_kernel<<<1, 32>>>();
    fc_kernel<<<2048, 256>>>(W_fc, b_fc, out);
}